// round 16
// baseline (speedup 1.0000x reference)
#include <cuda_runtime.h>
#include <cuda_fp16.h>
#include <cstdint>

#define NB 2
#define NC 256
#define HW 2304   // 48*48
#define WD 48
#define NPIX (NB * HW)   // 4608

// ---------------- device scratch ----------------
__device__ float g_q[NB * NC * HW];
__device__ float g_k[NB * NC * HW];
__device__ float g_v[NB * NC * HW];
__device__ __half g_x16[NB * NC * HW];     // x in fp16, same layout
__device__ __half g_w[768 * 256];          // [wq;wk;wv] fp16

__device__ __forceinline__ uint32_t smem_u32(const void* p) {
    uint32_t a;
    asm("{ .reg .u64 t; cvta.to.shared.u64 t, %1; cvt.u32.u64 %0, t; }"
        : "=r"(a) : "l"(p));
    return a;
}
__device__ __forceinline__ uint32_t pack_h2(__half a, __half b) {
    return ((uint32_t)*(uint16_t*)&b << 16) | *(uint16_t*)&a;
}

// ---------------------------------------------------------------------------
// prep (R15-measured 5.2us): z<2 -> streaming x fp32->fp16; z==2 -> weights.
// grid (72, 8, 3), block 256.
// ---------------------------------------------------------------------------
__global__ __launch_bounds__(256) void prep_kernel(
    const float* __restrict__ x, const float* __restrict__ wq,
    const float* __restrict__ wk, const float* __restrict__ wv)
{
    int tid = threadIdx.x;
    if (blockIdx.z == 2) {
        int gid = (blockIdx.y * 72 + blockIdx.x) * 256 + tid;
        int lin = gid * 2;
        if (lin < 768 * 256) {
            int o = lin >> 8;
            int c = lin & 255;
            const float* src = (o < 256) ? (wq + o * 256)
                              : (o < 512) ? (wk + (o - 256) * 256)
                                          : (wv + (o - 512) * 256);
            float2 v = *(const float2*)(src + c);
            ((uint32_t*)g_w)[gid] = pack_h2(__float2half_rn(v.x),
                                            __float2half_rn(v.y));
        }
        return;
    }
    int b = blockIdx.z;
    size_t gid = (size_t)(blockIdx.y * 72 + blockIdx.x) * 256 + tid;
    size_t base = (size_t)b * NC * HW + gid * 4;
    float4 v = *(const float4*)(x + base);
    uint2 r;
    r.x = pack_h2(__float2half_rn(v.x), __float2half_rn(v.y));
    r.y = pack_h2(__float2half_rn(v.z), __float2half_rn(v.w));
    *(uint2*)((char*)g_x16 + base * 2) = r;
}

// ---------------------------------------------------------------------------
// GEMM (R15-verbatim): mma.sync m16n8k16 f16 single pass, B via
// ldmatrix.x4.trans from k-major tiles. grid (36,12), 256 thr, 3 CTA/SM.
// ---------------------------------------------------------------------------
#define A_TILE_B 9216              // 64 oc rows * 144B
#define B_TILE_B 17408             // 64 c rows * 272B
#define GEMM_SMEM (A_TILE_B + B_TILE_B)   // 26624

__device__ __forceinline__ void mma_f16(float* d, const uint32_t* a,
                                        const uint32_t* b) {
    asm volatile(
        "mma.sync.aligned.m16n8k16.row.col.f32.f16.f16.f32 "
        "{%0,%1,%2,%3}, {%4,%5,%6,%7}, {%8,%9}, {%0,%1,%2,%3};"
        : "+f"(d[0]), "+f"(d[1]), "+f"(d[2]), "+f"(d[3])
        : "r"(a[0]), "r"(a[1]), "r"(a[2]), "r"(a[3]), "r"(b[0]), "r"(b[1]));
}

__global__ __launch_bounds__(256, 3) void gemm_kernel() {
    extern __shared__ char sm[];
    uint32_t uS = smem_u32(sm);

    int tid = threadIdx.x;
    int l   = tid & 31;
    int wid = tid >> 5;
    int wm  = wid >> 2;
    int wn  = wid & 3;

    int N0 = blockIdx.x * 128;
    int M0 = blockIdx.y * 64;

    int b   = N0 / HW;
    int pl0 = N0 - b * HW;

    const char* aw = (const char*)g_w + (size_t)M0 * 512;
    const char* bx = (const char*)g_x16 + ((size_t)b * NC * HW + pl0) * 2;

    float acc[2][4][4];
    #pragma unroll
    for (int i = 0; i < 2; i++)
        #pragma unroll
        for (int j = 0; j < 4; j++)
            #pragma unroll
            for (int r = 0; r < 4; r++) acc[i][j][r] = 0.f;

    uint32_t aLane = (uint32_t)((wm * 32 + (l & 15)) * 144 + (l >> 4) * 16);
    uint32_t bLane = (uint32_t)((((l >> 3) & 1) * 8 + (l & 7)) * 272
                                + (wn * 32 + ((l >> 4) & 1) * 8) * 2);

    for (int kt = 0; kt < 4; kt++) {
        __syncthreads();
        #pragma unroll
        for (int it = 0; it < 6; it++) {
            int lin = it * 256 + tid;
            if (lin < 512) {
                int row = lin >> 3;
                int ch  = lin & 7;
                uint4 v = *(const uint4*)(aw + row * 512 + kt * 128 + ch * 16);
                *(uint4*)(sm + row * 144 + ch * 16) = v;
            } else {
                int rem = lin - 512;
                int row = rem >> 4;
                int ch  = rem & 15;
                uint4 v = *(const uint4*)(bx + (size_t)(kt * 64 + row) * 4608
                                          + ch * 16);
                *(uint4*)(sm + A_TILE_B + row * 272 + ch * 16) = v;
            }
        }
        __syncthreads();

        uint32_t aBase = uS + aLane;
        uint32_t bBase = uS + A_TILE_B + bLane;
        #pragma unroll
        for (int ks = 0; ks < 4; ks++) {
            uint32_t af[2][4];
            uint32_t bf[4][2];
            #pragma unroll
            for (int i = 0; i < 2; i++) {
                uint32_t ad = aBase + i * (16 * 144) + ks * 32;
                asm volatile(
                    "ldmatrix.sync.aligned.m8n8.x4.shared.b16 "
                    "{%0,%1,%2,%3}, [%4];"
                    : "=r"(af[i][0]), "=r"(af[i][1]),
                      "=r"(af[i][2]), "=r"(af[i][3]) : "r"(ad));
            }
            #pragma unroll
            for (int jp = 0; jp < 2; jp++) {
                uint32_t bd = bBase + jp * 32 + ks * (16 * 272);
                asm volatile(
                    "ldmatrix.sync.aligned.m8n8.x4.trans.shared.b16 "
                    "{%0,%1,%2,%3}, [%4];"
                    : "=r"(bf[2 * jp][0]), "=r"(bf[2 * jp][1]),
                      "=r"(bf[2 * jp + 1][0]), "=r"(bf[2 * jp + 1][1])
                    : "r"(bd));
            }
            #pragma unroll
            for (int i = 0; i < 2; i++)
                #pragma unroll
                for (int j = 0; j < 4; j++)
                    mma_f16(acc[i][j], af[i], bf[j]);
        }
    }

    float* obuf = (M0 < 256) ? g_q : (M0 < 512) ? g_k : g_v;
    int ol = M0 & 255;
    int g  = l >> 2;
    int tc = l & 3;
    float* base = obuf + (size_t)b * NC * HW;

    #pragma unroll
    for (int i = 0; i < 2; i++) {
        int oc0 = ol + wm * 32 + i * 16 + g;
        #pragma unroll
        for (int j = 0; j < 4; j++) {
            int pix = pl0 + wn * 32 + j * 8 + tc * 2;
            *(float2*)(base + (size_t)oc0 * HW + pix) =
                make_float2(acc[i][j][0], acc[i][j][1]);
            *(float2*)(base + (size_t)(oc0 + 8) * HW + pix) =
                make_float2(acc[i][j][2], acc[i][j][3]);
        }
    }
}

// ---------------------------------------------------------------------------
// Attention v7: qb[4][7] table removed -> ~50 live regs -> 4 CTA/SM
// (36 warps/SM, 2 waves instead of 3). Same tap structure otherwise.
// USEH: qlb[o]=ql[o]*bias[kh] per kh (4 FMUL/kh).
// USEW: t = ql*(k+bw) (+1 op/tap, fma pipe has headroom).
// ---------------------------------------------------------------------------
template <bool USEH>
__device__ __forceinline__ void attn_body(
    const float* __restrict__ ks, const float* __restrict__ vs,
    const float* __restrict__ qrow, float* __restrict__ orow,
    const float* bias, int r, int w0)
{
    const float LOG2E = 1.4426950408889634f;
    float4 q4 = *(const float4*)(qrow + w0);
    float ql[4] = {q4.x * LOG2E, q4.y * LOG2E, q4.z * LOG2E, q4.w * LOG2E};

    float ssum[4] = {0.f, 0.f, 0.f, 0.f};
    float avec[4] = {0.f, 0.f, 0.f, 0.f};

    #pragma unroll
    for (int kh = 0; kh < 7; kh++) {
        const float* kr = &ks[(r + kh) * 56 + w0];
        const float* vr = &vs[(r + kh) * 56 + w0];
        float kvv[12], vvv[12];
        {
            float4 t0 = *(const float4*)(kr);
            float4 t1 = *(const float4*)(kr + 4);
            float4 t2 = *(const float4*)(kr + 8);
            kvv[0]=t0.x; kvv[1]=t0.y; kvv[2]=t0.z; kvv[3]=t0.w;
            kvv[4]=t1.x; kvv[5]=t1.y; kvv[6]=t1.z; kvv[7]=t1.w;
            kvv[8]=t2.x; kvv[9]=t2.y; kvv[10]=t2.z; kvv[11]=t2.w;
            float4 u0 = *(const float4*)(vr);
            float4 u1 = *(const float4*)(vr + 4);
            float4 u2 = *(const float4*)(vr + 8);
            vvv[0]=u0.x; vvv[1]=u0.y; vvv[2]=u0.z; vvv[3]=u0.w;
            vvv[4]=u1.x; vvv[5]=u1.y; vvv[6]=u1.z; vvv[7]=u1.w;
            vvv[8]=u2.x; vvv[9]=u2.y; vvv[10]=u2.z; vvv[11]=u2.w;
        }
        float qlb[4];
        if (USEH) {
            float bh = bias[kh];
            #pragma unroll
            for (int o = 0; o < 4; o++) qlb[o] = ql[o] * bh;
        }
        #pragma unroll
        for (int kw = 0; kw < 7; kw++) {
            float bw = USEH ? 0.f : bias[kw];
            #pragma unroll
            for (int o = 0; o < 4; o++) {
                int idx = o + kw + 1;
                float t;
                if (USEH) t = fmaf(ql[o], kvv[idx], qlb[o]);
                else      t = ql[o] * (kvv[idx] + bw);
                float e;
                asm("ex2.approx.f32 %0, %1;" : "=f"(e) : "f"(t));
                ssum[o] += e;
                avec[o] = fmaf(e, vvv[idx], avec[o]);
            }
        }
    }
    float inv[4];
    #pragma unroll
    for (int o = 0; o < 4; o++)
        asm("rcp.approx.f32 %0, %1;" : "=f"(inv[o]) : "f"(ssum[o]));
    float4 rr = make_float4(avec[0] * inv[0], avec[1] * inv[1],
                            avec[2] * inv[2], avec[3] * inv[3]);
    *(float4*)(orow + w0) = rr;
}

__global__ __launch_bounds__(288, 4) void attn_kernel(
    const float* __restrict__ rel_h, const float* __restrict__ rel_w,
    float* __restrict__ out)
{
    __shared__ float kvbuf[2 * 30 * 56];
    float* ks = kvbuf;
    float* vs = kvbuf + 1680;

    int plane = blockIdx.x >> 1;
    int half  = blockIdx.x & 1;
    int y0    = half * 24;
    int ybase = y0 - 3;
    int c = plane & 255;
    bool useH = (c < 128);

    const float* kp = g_k + (size_t)plane * HW;
    const float* vp = g_v + (size_t)plane * HW;
    const float* qp = g_q + (size_t)plane * HW;
    float*       op = out + (size_t)plane * HW;

    int tid = threadIdx.x;

    #pragma unroll
    for (int i = tid; i < 840; i += 288)
        ((float4*)kvbuf)[i] = make_float4(0.f, 0.f, 0.f, 0.f);
    __syncthreads();
    for (int i = tid; i < 360; i += 288) {
        int r  = i / 12;
        int x4 = (i - r * 12) << 2;
        int gy = ybase + r;
        if ((unsigned)gy < 48u) {
            *(float4*)(ks + r * 56 + x4 + 4) = *(const float4*)(kp + gy * WD + x4);
            *(float4*)(vs + r * 56 + x4 + 4) = *(const float4*)(vp + gy * WD + x4);
        }
    }
    const float* rb = useH ? (rel_h + c * 7) : (rel_w + (c - 128) * 7);
    float bias[7];
    #pragma unroll
    for (int j = 0; j < 7; j++) bias[j] = rb[j];
    __syncthreads();

    int r  = tid / 12;
    int w0 = (tid - r * 12) << 2;
    int gy = y0 + r;
    const float* qrow = qp + gy * WD;
    float*       orow = op + gy * WD;

    if (useH) attn_body<true >(ks, vs, qrow, orow, bias, r, w0);
    else      attn_body<false>(ks, vs, qrow, orow, bias, r, w0);
}

extern "C" void kernel_launch(void* const* d_in, const int* in_sizes, int n_in,
                              void* d_out, int out_size) {
    const float* x  = (const float*)d_in[0];
    const float* wq = (const float*)d_in[1];
    const float* wk = (const float*)d_in[2];
    const float* wv = (const float*)d_in[3];
    const float* rh = (const float*)d_in[4];
    const float* rw = (const float*)d_in[5];

    cudaFuncSetAttribute(gemm_kernel, cudaFuncAttributeMaxDynamicSharedMemorySize,
                         GEMM_SMEM);

    prep_kernel<<<dim3(72, 8, 3), 256>>>(x, wq, wk, wv);
    gemm_kernel<<<dim3(36, 12), 256, GEMM_SMEM>>>();
    attn_kernel<<<1024, 288>>>(rh, rw, (float*)d_out);
}

// round 17
// speedup vs baseline: 1.0193x; 1.0193x over previous
#include <cuda_runtime.h>
#include <cuda_fp16.h>
#include <cstdint>

#define NB 2
#define NC 256
#define HW 2304   // 48*48
#define WD 48
#define NPIX (NB * HW)   // 4608

// ---------------- device scratch ----------------
__device__ float g_q[NB * NC * HW];
__device__ float g_k[NB * NC * HW];
__device__ float g_v[NB * NC * HW];
__device__ __half g_x16[NB * NC * HW];     // x in fp16, same layout
__device__ __half g_w[768 * 256];          // [wq;wk;wv] fp16

__device__ __forceinline__ uint32_t smem_u32(const void* p) {
    uint32_t a;
    asm("{ .reg .u64 t; cvta.to.shared.u64 t, %1; cvt.u32.u64 %0, t; }"
        : "=r"(a) : "l"(p));
    return a;
}
__device__ __forceinline__ uint32_t pack_h2(__half a, __half b) {
    return ((uint32_t)*(uint16_t*)&b << 16) | *(uint16_t*)&a;
}

// ---------------------------------------------------------------------------
// prep v4: flat fp32->fp16 stream over x and [wq;wk;wv] as ONE item space.
// 344064 float4 items = 672 blocks x 256 threads x 2 items (exact).
// Both loads issued before converts -> MLP=2/thread, 4.5 blocks/SM.
// ---------------------------------------------------------------------------
#define PREP_ITEMS 344064          // 294912 (x) + 49152 (w) float4s
#define PREP_HALF  172032

__global__ __launch_bounds__(256) void prep_kernel(
    const float* __restrict__ x, const float* __restrict__ wq,
    const float* __restrict__ wk, const float* __restrict__ wv)
{
    int gid = blockIdx.x * 256 + threadIdx.x;   // 0..172031

    const float4* src[2];
    uint2* dst[2];
    #pragma unroll
    for (int s = 0; s < 2; s++) {
        int i = gid + s * PREP_HALF;
        if (i < 294912) {
            src[s] = (const float4*)x + i;
            dst[s] = (uint2*)g_x16 + i;
        } else {
            int j   = i - 294912;          // 0..49151
            int sel = j >> 14;             // 16384 float4 per weight matrix
            int jj  = j & 16383;
            const float* w = (sel == 0) ? wq : (sel == 1) ? wk : wv;
            src[s] = (const float4*)w + jj;
            dst[s] = (uint2*)g_w + j;
        }
    }
    float4 v0 = *src[0];
    float4 v1 = *src[1];
    uint2 r0, r1;
    r0.x = pack_h2(__float2half_rn(v0.x), __float2half_rn(v0.y));
    r0.y = pack_h2(__float2half_rn(v0.z), __float2half_rn(v0.w));
    r1.x = pack_h2(__float2half_rn(v1.x), __float2half_rn(v1.y));
    r1.y = pack_h2(__float2half_rn(v1.z), __float2half_rn(v1.w));
    *dst[0] = r0;
    *dst[1] = r1;
}

// ---------------------------------------------------------------------------
// GEMM (R15-verbatim, ~6.8us = HMMA floor): mma.sync m16n8k16 f16 single
// pass, B via ldmatrix.x4.trans from k-major tiles. grid (36,12), 256 thr.
// ---------------------------------------------------------------------------
#define A_TILE_B 9216              // 64 oc rows * 144B
#define B_TILE_B 17408             // 64 c rows * 272B
#define GEMM_SMEM (A_TILE_B + B_TILE_B)   // 26624

__device__ __forceinline__ void mma_f16(float* d, const uint32_t* a,
                                        const uint32_t* b) {
    asm volatile(
        "mma.sync.aligned.m16n8k16.row.col.f32.f16.f16.f32 "
        "{%0,%1,%2,%3}, {%4,%5,%6,%7}, {%8,%9}, {%0,%1,%2,%3};"
        : "+f"(d[0]), "+f"(d[1]), "+f"(d[2]), "+f"(d[3])
        : "r"(a[0]), "r"(a[1]), "r"(a[2]), "r"(a[3]), "r"(b[0]), "r"(b[1]));
}

__global__ __launch_bounds__(256, 3) void gemm_kernel() {
    extern __shared__ char sm[];
    uint32_t uS = smem_u32(sm);

    int tid = threadIdx.x;
    int l   = tid & 31;
    int wid = tid >> 5;
    int wm  = wid >> 2;
    int wn  = wid & 3;

    int N0 = blockIdx.x * 128;
    int M0 = blockIdx.y * 64;

    int b   = N0 / HW;
    int pl0 = N0 - b * HW;

    const char* aw = (const char*)g_w + (size_t)M0 * 512;
    const char* bx = (const char*)g_x16 + ((size_t)b * NC * HW + pl0) * 2;

    float acc[2][4][4];
    #pragma unroll
    for (int i = 0; i < 2; i++)
        #pragma unroll
        for (int j = 0; j < 4; j++)
            #pragma unroll
            for (int r = 0; r < 4; r++) acc[i][j][r] = 0.f;

    uint32_t aLane = (uint32_t)((wm * 32 + (l & 15)) * 144 + (l >> 4) * 16);
    uint32_t bLane = (uint32_t)((((l >> 3) & 1) * 8 + (l & 7)) * 272
                                + (wn * 32 + ((l >> 4) & 1) * 8) * 2);

    for (int kt = 0; kt < 4; kt++) {
        __syncthreads();
        #pragma unroll
        for (int it = 0; it < 6; it++) {
            int lin = it * 256 + tid;
            if (lin < 512) {
                int row = lin >> 3;
                int ch  = lin & 7;
                uint4 v = *(const uint4*)(aw + row * 512 + kt * 128 + ch * 16);
                *(uint4*)(sm + row * 144 + ch * 16) = v;
            } else {
                int rem = lin - 512;
                int row = rem >> 4;
                int ch  = rem & 15;
                uint4 v = *(const uint4*)(bx + (size_t)(kt * 64 + row) * 4608
                                          + ch * 16);
                *(uint4*)(sm + A_TILE_B + row * 272 + ch * 16) = v;
            }
        }
        __syncthreads();

        uint32_t aBase = uS + aLane;
        uint32_t bBase = uS + A_TILE_B + bLane;
        #pragma unroll
        for (int ks = 0; ks < 4; ks++) {
            uint32_t af[2][4];
            uint32_t bf[4][2];
            #pragma unroll
            for (int i = 0; i < 2; i++) {
                uint32_t ad = aBase + i * (16 * 144) + ks * 32;
                asm volatile(
                    "ldmatrix.sync.aligned.m8n8.x4.shared.b16 "
                    "{%0,%1,%2,%3}, [%4];"
                    : "=r"(af[i][0]), "=r"(af[i][1]),
                      "=r"(af[i][2]), "=r"(af[i][3]) : "r"(ad));
            }
            #pragma unroll
            for (int jp = 0; jp < 2; jp++) {
                uint32_t bd = bBase + jp * 32 + ks * (16 * 272);
                asm volatile(
                    "ldmatrix.sync.aligned.m8n8.x4.trans.shared.b16 "
                    "{%0,%1,%2,%3}, [%4];"
                    : "=r"(bf[2 * jp][0]), "=r"(bf[2 * jp][1]),
                      "=r"(bf[2 * jp + 1][0]), "=r"(bf[2 * jp + 1][1])
                    : "r"(bd));
            }
            #pragma unroll
            for (int i = 0; i < 2; i++)
                #pragma unroll
                for (int j = 0; j < 4; j++)
                    mma_f16(acc[i][j], af[i], bf[j]);
        }
    }

    float* obuf = (M0 < 256) ? g_q : (M0 < 512) ? g_k : g_v;
    int ol = M0 & 255;
    int g  = l >> 2;
    int tc = l & 3;
    float* base = obuf + (size_t)b * NC * HW;

    #pragma unroll
    for (int i = 0; i < 2; i++) {
        int oc0 = ol + wm * 32 + i * 16 + g;
        #pragma unroll
        for (int j = 0; j < 4; j++) {
            int pix = pl0 + wn * 32 + j * 8 + tc * 2;
            *(float2*)(base + (size_t)oc0 * HW + pix) =
                make_float2(acc[i][j][0], acc[i][j][1]);
            *(float2*)(base + (size_t)(oc0 + 8) * HW + pix) =
                make_float2(acc[i][j][2], acc[i][j][3]);
        }
    }
}

// ---------------------------------------------------------------------------
// Attention (R15-verbatim, FROZEN): 1024 blocks x 288 threads, one 4px
// group/thread, 72 regs, 3 CTA/SM, qb table, rcp.approx epilogue.
// ---------------------------------------------------------------------------
template <bool USEH>
__device__ __forceinline__ void attn_body(
    const float* __restrict__ ks, const float* __restrict__ vs,
    const float* __restrict__ qrow, float* __restrict__ orow,
    const float* bias, int r, int w0)
{
    const float LOG2E = 1.4426950408889634f;
    float4 q4 = *(const float4*)(qrow + w0);
    float ql[4] = {q4.x * LOG2E, q4.y * LOG2E, q4.z * LOG2E, q4.w * LOG2E};
    float qb[4][7];
    #pragma unroll
    for (int o = 0; o < 4; o++)
        #pragma unroll
        for (int j = 0; j < 7; j++) qb[o][j] = ql[o] * bias[j];

    float ssum[4] = {0.f, 0.f, 0.f, 0.f};
    float avec[4] = {0.f, 0.f, 0.f, 0.f};

    #pragma unroll
    for (int kh = 0; kh < 7; kh++) {
        const float* kr = &ks[(r + kh) * 56 + w0];
        const float* vr = &vs[(r + kh) * 56 + w0];
        float kvv[12], vvv[12];
        {
            float4 t0 = *(const float4*)(kr);
            float4 t1 = *(const float4*)(kr + 4);
            float4 t2 = *(const float4*)(kr + 8);
            kvv[0]=t0.x; kvv[1]=t0.y; kvv[2]=t0.z; kvv[3]=t0.w;
            kvv[4]=t1.x; kvv[5]=t1.y; kvv[6]=t1.z; kvv[7]=t1.w;
            kvv[8]=t2.x; kvv[9]=t2.y; kvv[10]=t2.z; kvv[11]=t2.w;
            float4 u0 = *(const float4*)(vr);
            float4 u1 = *(const float4*)(vr + 4);
            float4 u2 = *(const float4*)(vr + 8);
            vvv[0]=u0.x; vvv[1]=u0.y; vvv[2]=u0.z; vvv[3]=u0.w;
            vvv[4]=u1.x; vvv[5]=u1.y; vvv[6]=u1.z; vvv[7]=u1.w;
            vvv[8]=u2.x; vvv[9]=u2.y; vvv[10]=u2.z; vvv[11]=u2.w;
        }
        #pragma unroll
        for (int kw = 0; kw < 7; kw++) {
            #pragma unroll
            for (int o = 0; o < 4; o++) {
                int idx = o + kw + 1;
                float qbb = USEH ? qb[o][kh] : qb[o][kw];
                float t = fmaf(ql[o], kvv[idx], qbb);
                float e;
                asm("ex2.approx.f32 %0, %1;" : "=f"(e) : "f"(t));
                ssum[o] += e;
                avec[o] = fmaf(e, vvv[idx], avec[o]);
            }
        }
    }
    float inv[4];
    #pragma unroll
    for (int o = 0; o < 4; o++)
        asm("rcp.approx.f32 %0, %1;" : "=f"(inv[o]) : "f"(ssum[o]));
    float4 rr = make_float4(avec[0] * inv[0], avec[1] * inv[1],
                            avec[2] * inv[2], avec[3] * inv[3]);
    *(float4*)(orow + w0) = rr;
}

__global__ __launch_bounds__(288) void attn_kernel(
    const float* __restrict__ rel_h, const float* __restrict__ rel_w,
    float* __restrict__ out)
{
    __shared__ float kvbuf[2 * 30 * 56];
    float* ks = kvbuf;
    float* vs = kvbuf + 1680;

    int plane = blockIdx.x >> 1;
    int half  = blockIdx.x & 1;
    int y0    = half * 24;
    int ybase = y0 - 3;
    int c = plane & 255;
    bool useH = (c < 128);

    const float* kp = g_k + (size_t)plane * HW;
    const float* vp = g_v + (size_t)plane * HW;
    const float* qp = g_q + (size_t)plane * HW;
    float*       op = out + (size_t)plane * HW;

    int tid = threadIdx.x;

    #pragma unroll
    for (int i = tid; i < 840; i += 288)
        ((float4*)kvbuf)[i] = make_float4(0.f, 0.f, 0.f, 0.f);
    __syncthreads();
    for (int i = tid; i < 360; i += 288) {
        int r  = i / 12;
        int x4 = (i - r * 12) << 2;
        int gy = ybase + r;
        if ((unsigned)gy < 48u) {
            *(float4*)(ks + r * 56 + x4 + 4) = *(const float4*)(kp + gy * WD + x4);
            *(float4*)(vs + r * 56 + x4 + 4) = *(const float4*)(vp + gy * WD + x4);
        }
    }
    const float* rb = useH ? (rel_h + c * 7) : (rel_w + (c - 128) * 7);
    float bias[7];
    #pragma unroll
    for (int j = 0; j < 7; j++) bias[j] = rb[j];
    __syncthreads();

    int r  = tid / 12;
    int w0 = (tid - r * 12) << 2;
    int gy = y0 + r;
    const float* qrow = qp + gy * WD;
    float*       orow = op + gy * WD;

    if (useH) attn_body<true >(ks, vs, qrow, orow, bias, r, w0);
    else      attn_body<false>(ks, vs, qrow, orow, bias, r, w0);
}

extern "C" void kernel_launch(void* const* d_in, const int* in_sizes, int n_in,
                              void* d_out, int out_size) {
    const float* x  = (const float*)d_in[0];
    const float* wq = (const float*)d_in[1];
    const float* wk = (const float*)d_in[2];
    const float* wv = (const float*)d_in[3];
    const float* rh = (const float*)d_in[4];
    const float* rw = (const float*)d_in[5];

    cudaFuncSetAttribute(gemm_kernel, cudaFuncAttributeMaxDynamicSharedMemorySize,
                         GEMM_SMEM);

    prep_kernel<<<672, 256>>>(x, wq, wk, wv);
    gemm_kernel<<<dim3(36, 12), 256, GEMM_SMEM>>>();
    attn_kernel<<<1024, 288>>>(rh, rw, (float*)d_out);
}